// round 5
// baseline (speedup 1.0000x reference)
#include <cuda_runtime.h>
#include <cstdint>

// Problem constants (fixed by the reference)
#define B_DIM 16
#define S_DIM 4096
#define H_DIM 768
#define NUM_WORDS 2048          // S/2
#define VEC (H_DIM / 4)         // 192 float4 per row
#define W_PB 16                 // words per block

// Single fused kernel: one block per (16 contiguous words, batch).
//
// word_ids[b, 1..S-2] is non-decreasing with contiguous values 0..maxw
// (cumsum construction); positions 0 and S-1 are -1 (CLS/SEP, dropped).
// Threads c<=16 binary-search the start token of words w0..w0+16 (monotone
// by construction, lower_bound(w) == S-1 for w > maxw -> empty words ->
// zero rows, matching the reference). The 16 words then cover one contiguous
// token range: the block streams it sequentially with a depth-3 prefetch
// ring (3 outstanding loads/thread), flushing the register accumulator at
// each block-uniform word boundary.
__global__ __launch_bounds__(VEC, 8) void seg_mean_fused_kernel(
    const float4* __restrict__ hs,   // [B, S, VEC]
    const int*    __restrict__ wid,  // [B, S]
    float4*       __restrict__ out)  // [B, NUM_WORDS, VEC]
{
    const int b  = blockIdx.y;
    const int w0 = blockIdx.x * W_PB;
    const int c  = threadIdx.x;

    __shared__ int sm[W_PB + 1];
    if (c <= W_PB) {
        const int* __restrict__ row = wid + (size_t)b * S_DIM;
        const int target = w0 + c;
        int lo = 1, hi = S_DIM - 1;          // search [1, S-1)
        while (lo < hi) {
            int mid = (lo + hi) >> 1;
            if (__ldg(row + mid) < target) lo = mid + 1; else hi = mid;
        }
        sm[c] = lo;                          // first token with word >= target
    }
    __syncthreads();

    const float4* __restrict__ base =
        hs + (size_t)b * S_DIM * VEC + c;
    float4* __restrict__ ob =
        out + ((size_t)b * NUM_WORDS + w0) * VEC + c;

    int t = sm[0];
    const int tEnd = sm[W_PB];
    const int last = tEnd - 1;               // valid only when tEnd > t

    // Depth-3 prefetch ring (clamped tail addresses stay in-bounds).
    float4 v0 = make_float4(0.f, 0.f, 0.f, 0.f);
    float4 v1 = v0, v2 = v0;
    if (t < tEnd) {
        v0 = __ldcs(base + (size_t)t * VEC);
        v1 = __ldcs(base + (size_t)min(t + 1, last) * VEC);
        v2 = __ldcs(base + (size_t)min(t + 2, last) * VEC);
    }

    int prev = t;
#pragma unroll 1
    for (int i = 0; i < W_PB; ++i) {
        const int e = sm[i + 1];
        float4 acc = make_float4(0.f, 0.f, 0.f, 0.f);
        while (t < e) {
            float4 cur = v0;
            v0 = v1;
            v1 = v2;
            v2 = __ldcs(base + (size_t)min(t + 3, last) * VEC);
            ++t;
            acc.x += cur.x; acc.y += cur.y;
            acc.z += cur.z; acc.w += cur.w;
        }
        const int cnt = e - prev;
        prev = e;
        const float inv = (cnt > 0) ? (1.0f / (float)cnt) : 0.0f;
        float4 r;
        r.x = acc.x * inv; r.y = acc.y * inv;
        r.z = acc.z * inv; r.w = acc.w * inv;
        __stcs(ob + (size_t)i * VEC, r);
    }
}

extern "C" void kernel_launch(void* const* d_in, const int* in_sizes, int n_in,
                              void* d_out, int out_size)
{
    const float* hs  = (const float*)d_in[0];   // hidden_states [B,S,H] f32
    const int*   wid = (const int*)d_in[1];     // word_ids [B,S] i32
    float*       out = (float*)d_out;           // [B, NUM_WORDS, H] f32

    dim3 grid(NUM_WORDS / W_PB, B_DIM);
    seg_mean_fused_kernel<<<grid, VEC>>>((const float4*)hs, wid, (float4*)out);
}

// round 7
// speedup vs baseline: 1.0402x; 1.0402x over previous
#include <cuda_runtime.h>
#include <cstdint>

// Problem constants (fixed by the reference)
#define B_DIM 16
#define S_DIM 4096
#define H_DIM 768
#define NUM_WORDS 2048          // S/2
#define ROW_BYTES (H_DIM * 4)   // 3072 bytes per token/word row
#define VEC (H_DIM / 4)         // 192 threads: one 16B chunk per thread
#define W_PB 4                  // words per block (fine-grained -> ~7 waves)

// One block per (4 contiguous words, batch); grid 512 x 16 = 8192 blocks.
//
// word_ids[b, 1..S-2] is non-decreasing with contiguous values 0..maxw
// (cumsum construction); positions 0 and S-1 are -1 (CLS/SEP, dropped).
// Threads c<=4 binary-search the start token of words w0..w0+4; for w > maxw
// lower_bound == S-1, so absent words get cnt=0 -> zero rows (matches ref).
// The 4 words cover one contiguous token range: stream it with an unroll-2
// loop (2 independent 16B loads in flight, no ring MOVs), accumulate with
// packed f32x2 adds, flush at each block-uniform word boundary.
__global__ __launch_bounds__(VEC) void seg_mean_fused_kernel(
    const char* __restrict__ hs,   // [B, S, H] f32 as bytes
    const int*  __restrict__ wid,  // [B, S]
    char*       __restrict__ out)  // [B, NUM_WORDS, H] f32 as bytes
{
    const int b  = blockIdx.y;
    const int w0 = blockIdx.x * W_PB;
    const int c  = threadIdx.x;

    __shared__ int sm[W_PB + 1];
    if (c <= W_PB) {
        const int* __restrict__ row = wid + (size_t)b * S_DIM;
        const int target = w0 + c;
        int lo = 1, hi = S_DIM - 1;          // search [1, S-1)
        while (lo < hi) {
            int mid = (lo + hi) >> 1;
            if (__ldg(row + mid) < target) lo = mid + 1; else hi = mid;
        }
        sm[c] = lo;
    }
    __syncthreads();

    const char* __restrict__ base =
        hs + (size_t)b * S_DIM * ROW_BYTES + c * 16;
    char* __restrict__ ob =
        out + ((size_t)b * NUM_WORDS + w0) * ROW_BYTES + c * 16;

    int t = sm[0];
    const char* p = base + (long)t * ROW_BYTES;   // running byte pointer

#pragma unroll
    for (int i = 0; i < W_PB; ++i) {
        const int e = sm[i + 1];
        const int cnt = e - t;

        unsigned long long a0 = 0ull, a1 = 0ull;  // packed f32x2 accumulators

        // unroll-2: two independent streaming 16B loads per iteration
        while (t + 2 <= e) {
            unsigned long long x0, x1, y0, y1;
            asm volatile("ld.global.cs.v2.u64 {%0,%1}, [%2];"
                         : "=l"(x0), "=l"(x1) : "l"(p));
            asm volatile("ld.global.cs.v2.u64 {%0,%1}, [%2];"
                         : "=l"(y0), "=l"(y1) : "l"(p + ROW_BYTES));
            asm("add.rn.f32x2 %0, %0, %1;" : "+l"(a0) : "l"(x0));
            asm("add.rn.f32x2 %0, %0, %1;" : "+l"(a1) : "l"(x1));
            asm("add.rn.f32x2 %0, %0, %1;" : "+l"(a0) : "l"(y0));
            asm("add.rn.f32x2 %0, %0, %1;" : "+l"(a1) : "l"(y1));
            p += 2 * ROW_BYTES;
            t += 2;
        }
        if (t < e) {
            unsigned long long x0, x1;
            asm volatile("ld.global.cs.v2.u64 {%0,%1}, [%2];"
                         : "=l"(x0), "=l"(x1) : "l"(p));
            asm("add.rn.f32x2 %0, %0, %1;" : "+l"(a0) : "l"(x0));
            asm("add.rn.f32x2 %0, %0, %1;" : "+l"(a1) : "l"(x1));
            p += ROW_BYTES;
            ++t;
        }

        // scale by 1/cnt (0 for empty words) with packed f32x2 muls
        const float inv = (cnt > 0) ? (1.0f / (float)cnt) : 0.0f;
        const unsigned int ib = __float_as_uint(inv);
        const unsigned long long ip =
            ((unsigned long long)ib << 32) | (unsigned long long)ib;
        asm("mul.rn.f32x2 %0, %0, %1;" : "+l"(a0) : "l"(ip));
        asm("mul.rn.f32x2 %0, %0, %1;" : "+l"(a1) : "l"(ip));

        asm volatile("st.global.cs.v2.u64 [%0], {%1,%2};"
                     :: "l"(ob + (long)i * ROW_BYTES), "l"(a0), "l"(a1)
                     : "memory");
    }
}

extern "C" void kernel_launch(void* const* d_in, const int* in_sizes, int n_in,
                              void* d_out, int out_size)
{
    const char* hs  = (const char*)d_in[0];   // hidden_states [B,S,H] f32
    const int*  wid = (const int*)d_in[1];    // word_ids [B,S] i32
    char*       out = (char*)d_out;           // [B, NUM_WORDS, H] f32

    dim3 grid(NUM_WORDS / W_PB, B_DIM);
    seg_mean_fused_kernel<<<grid, VEC>>>(hs, wid, out);
}